// round 8
// baseline (speedup 1.0000x reference)
#include <cuda_runtime.h>
#include <cuda_fp16.h>
#include <cstdint>

// Soft decision tree forward via mma.sync fp16 (family-common sm_103;
// tcgen05 unavailable in this toolchain path).
// Chain nodes (2^k)-1, k=0..5 -> N = 6*64 = 384.
// GEMM H = X[65536x128] @ W1cat[128x384], fp16 x fp16 -> fp32 accumulate.
// Fused epilogue: relu -> dot W2 -> sigmoid -> 6-level leaf fold.
// R8: M=64 CTAs, 192 threads (1 warp per node), __launch_bounds__(192,2)
// -> 2 CTAs/SM; cross-CTA overlap hides X-staging + epilogue exposure.

#define THREADS 192
#define M_CTA   64
#define KDIM    128
#define NTOT    384
#define NCTAS   1024
#define XPITCH  288      // bytes/row (72 words = 8 mod 32: conflict-free lds64)
#define WPITCH  96       // bytes/row (24 words: banks partition cleanly)

// W1 (live nodes) fp16, [n=384][k=128], k permuted within 16-blocks so that
// pairs (2t4,2t4+1) and (2t4+8,2t4+9) are adjacent -> B frags = one LDS.64.
__device__ __align__(16) __half g_Wh[NTOT * KDIM];

// ---- smem layout (bytes) ----
#define OFF_B1    0
#define OFF_W2    1536
#define OFF_B2    3072
#define OFF_LEAF  3104
#define OFF_RS    3360                 // rowsum 6*68*4 = 1632 -> 4992
#define OFF_X     5120                 // 64 rows * 288B = 18432 -> 23552
#define OFF_W0    23552                // 384 rows * 96B = 36864
#define OFF_W1    60416
#define SMEM_BYTES 97280               // x2 CTAs = 190KB/SM (fits 228KB)

// ---------------- helpers ----------------
__device__ __forceinline__ uint32_t smem_u32_of(const void* p) {
    uint32_t a;
    asm("{ .reg .u64 t; cvta.to.shared.u64 t, %1; cvt.u32.u64 %0, t; }"
        : "=r"(a) : "l"(p));
    return a;
}
__device__ __forceinline__ void cp_async16(uint32_t dst, const void* src) {
    asm volatile("cp.async.cg.shared.global [%0], [%1], 16;" :: "r"(dst), "l"(src));
}
__device__ __forceinline__ void lds64(uint32_t& a, uint32_t& b, uint32_t addr) {
    asm volatile("ld.shared.v2.u32 {%0,%1}, [%2];" : "=r"(a), "=r"(b) : "r"(addr));
}
__device__ __forceinline__ void sts32(uint32_t addr, uint32_t v) {
    asm volatile("st.shared.u32 [%0], %1;" :: "r"(addr), "r"(v));
}
__device__ __forceinline__ void mma_fp16(float* c, const uint32_t* a,
                                         uint32_t b0, uint32_t b1) {
    asm volatile(
        "mma.sync.aligned.m16n8k16.row.col.f32.f16.f16.f32 "
        "{%0,%1,%2,%3}, {%4,%5,%6,%7}, {%8,%9}, {%0,%1,%2,%3};"
        : "+f"(c[0]), "+f"(c[1]), "+f"(c[2]), "+f"(c[3])
        : "r"(a[0]), "r"(a[1]), "r"(a[2]), "r"(a[3]), "r"(b0), "r"(b1));
}

// ---------------- pre-kernel: W1 -> fp16, permuted k ----------------
__global__ void convert_w1_kernel(const float* __restrict__ W1) {
    int idx = blockIdx.x * blockDim.x + threadIdx.x;
    if (idx >= NTOT * KDIM) return;
    int k = idx & 127;
    int n = idx >> 7;
    int node = n >> 6, h = n & 63;
    int gnode = (1 << node) - 1;            // 0,1,3,7,15,31
    float v = W1[(size_t)gnode * (KDIM * 64) + (size_t)k * 64 + h];
    int blk = k >> 4, kk = k & 15, q = kk >> 1;
    int pos = (q & 3) * 2 + (q >> 2);
    g_Wh[n * KDIM + blk * 16 + pos * 2 + (kk & 1)] = __float2half_rn(v);
}

// ---------------- main kernel ----------------
__global__ __launch_bounds__(THREADS, 2)
void sdt_fp16_kernel(const float* __restrict__ x,
                     const float* __restrict__ b1,
                     const float* __restrict__ W2,
                     const float* __restrict__ b2,
                     const float* __restrict__ leaf,
                     float* __restrict__ out)
{
    extern __shared__ char smem[];
    const uint32_t sbase = smem_u32_of(smem);
    float* b1s    = (float*)(smem + OFF_B1);
    float* W2s    = (float*)(smem + OFF_W2);
    float* b2s    = (float*)(smem + OFF_B2);
    float* leafs  = (float*)(smem + OFF_LEAF);
    float* rowsum = (float*)(smem + OFF_RS);

    const int tid  = threadIdx.x;
    const int lane = tid & 31;
    const int wn   = tid >> 5;              // warp = node (0..5)
    const int g    = lane >> 2;
    const int t4   = lane & 3;
    const int rowbase = blockIdx.x * M_CTA;

    // ---- prologue: W chunk 0 cp.async ----
    #pragma unroll
    for (int it = 0; it < 8; it++) {
        int idx = tid + it * THREADS;       // 0..1535
        int row = idx >> 2, v = idx & 3;
        cp_async16(sbase + OFF_W0 + row * WPITCH + v * 16,
                   g_Wh + row * KDIM + v * 8);
    }
    asm volatile("cp.async.commit_group;" ::: "memory");

    // small tensors for the 6 live nodes
    for (int i = tid; i < NTOT; i += THREADS) {
        int node = i >> 6, h = i & 63;
        int gl = ((1 << node) - 1) * 64 + h;
        b1s[i] = b1[gl];
        W2s[i] = W2[gl];
    }
    if (tid < 6)  b2s[tid]   = b2[(1 << tid) - 1];
    if (tid < 64) leafs[tid] = leaf[tid];

    // ---- stage X (all 128 k), fp32 -> fp16, k-pair interleaved ----
    {
        const float4* xg = (const float4*)x;
        #pragma unroll
        for (int it = 0; it < 11; it++) {
            int idx = tid + it * THREADS;   // 0..2047
            if (idx < 2048) {
                int row = idx >> 5;         // 32 float4 per row
                int c4  = idx & 31;
                float4 v = xg[(size_t)(rowbase + row) * 32 + c4];
                __half2 h01 = __floats2half2_rn(v.x, v.y);
                __half2 h23 = __floats2half2_rn(v.z, v.w);
                int blk = c4 >> 2, m = c4 & 3;
                int pos_a = (m & 1) * 4 + (m >> 1);
                uint32_t a = sbase + OFF_X + row * XPITCH + blk * 32 + pos_a * 4;
                sts32(a,     *(uint32_t*)&h01);
                sts32(a + 8, *(uint32_t*)&h23);
            }
        }
    }

    float acc[4][8][4];
    #pragma unroll
    for (int mt = 0; mt < 4; mt++)
        #pragma unroll
        for (int nt = 0; nt < 8; nt++)
            #pragma unroll
            for (int j = 0; j < 4; j++) acc[mt][nt][j] = 0.0f;

    const uint32_t xb   = sbase + OFF_X + (uint32_t)(g * XPITCH + t4 * 8);
    const uint32_t wrow = (uint32_t)((wn * 64 + g) * WPITCH + t4 * 8);

    // ---- 4 k-chunks of 32, W double-buffered ----
    for (int kc = 0; kc < 4; kc++) {
        const int bb = kc & 1;
        asm volatile("cp.async.wait_group 0;" ::: "memory");
        __syncthreads();
        if (kc < 3) {   // prefetch chunk kc+1 into other buffer (overlaps compute)
            uint32_t wdst = sbase + (uint32_t)(bb ? OFF_W0 : OFF_W1);
            #pragma unroll
            for (int it = 0; it < 8; it++) {
                int idx = tid + it * THREADS;
                int row = idx >> 2, v = idx & 3;
                cp_async16(wdst + row * WPITCH + v * 16,
                           g_Wh + row * KDIM + (kc + 1) * 32 + v * 8);
            }
            asm volatile("cp.async.commit_group;" ::: "memory");
        }

        const uint32_t wb = sbase + (uint32_t)(bb ? OFF_W1 : OFF_W0) + wrow;
        #pragma unroll
        for (int ks = 0; ks < 2; ks++) {
            const uint32_t xo = (uint32_t)((kc * 2 + ks) * 32);
            const uint32_t ko = (uint32_t)(ks * 32);
            uint32_t A[4][4];
            #pragma unroll
            for (int mt = 0; mt < 4; mt++) {
                lds64(A[mt][0], A[mt][2], xb + (uint32_t)(mt * 16 * XPITCH) + xo);
                lds64(A[mt][1], A[mt][3], xb + (uint32_t)(mt * 16 * XPITCH) + 8 * XPITCH + xo);
            }
            #pragma unroll
            for (int nt = 0; nt < 8; nt++) {
                uint32_t b0, b1v_;
                lds64(b0, b1v_, wb + (uint32_t)(nt * 8 * WPITCH) + ko);
                #pragma unroll
                for (int mt = 0; mt < 4; mt++)
                    mma_fp16(acc[mt][nt], A[mt], b0, b1v_);
            }
        }
    }

    // ---- fused epilogue ----
    float b1v[16], W2v[16];
    #pragma unroll
    for (int nt = 0; nt < 8; nt++) {
        int col = wn * 64 + nt * 8 + t4 * 2;
        b1v[2 * nt]     = b1s[col];
        b1v[2 * nt + 1] = b1s[col + 1];
        W2v[2 * nt]     = W2s[col];
        W2v[2 * nt + 1] = W2s[col + 1];
    }
    __syncthreads();

    #pragma unroll
    for (int mt = 0; mt < 4; mt++) {
        float s0 = 0.0f, s1 = 0.0f;
        #pragma unroll
        for (int nt = 0; nt < 8; nt++) {
            s0 = fmaf(fmaxf(acc[mt][nt][0] + b1v[2 * nt], 0.0f),     W2v[2 * nt], s0);
            s0 = fmaf(fmaxf(acc[mt][nt][1] + b1v[2 * nt + 1], 0.0f), W2v[2 * nt + 1], s0);
            s1 = fmaf(fmaxf(acc[mt][nt][2] + b1v[2 * nt], 0.0f),     W2v[2 * nt], s1);
            s1 = fmaf(fmaxf(acc[mt][nt][3] + b1v[2 * nt + 1], 0.0f), W2v[2 * nt + 1], s1);
        }
        s0 += __shfl_xor_sync(0xffffffffu, s0, 1);
        s0 += __shfl_xor_sync(0xffffffffu, s0, 2);
        s1 += __shfl_xor_sync(0xffffffffu, s1, 1);
        s1 += __shfl_xor_sync(0xffffffffu, s1, 2);
        if (t4 == 0) {
            int r = mt * 16 + g;
            rowsum[wn * 68 + r]     = s0;
            rowsum[wn * 68 + r + 8] = s1;
        }
    }
    __syncthreads();

    if (tid < M_CTA) {
        float p[6];
        #pragma unroll
        for (int k = 0; k < 6; k++) {
            float z = rowsum[k * 68 + tid] + b2s[k];
            p[k] = 1.0f / (1.0f + __expf(-z));
        }
        float v[32];
        #pragma unroll
        for (int m = 0; m < 32; m++)
            v[m] = fmaf(p[0], leafs[2 * m + 1], (1.0f - p[0]) * leafs[2 * m]);
        #pragma unroll
        for (int k = 1; k < 6; k++) {
            int len = 32 >> k;
            #pragma unroll
            for (int m = 0; m < 32; m++)
                if (m < len)
                    v[m] = fmaf(p[k], v[2 * m + 1], (1.0f - p[k]) * v[2 * m]);
        }
        out[rowbase + tid] = v[0];
    }
}

// ---------------- launch ----------------
extern "C" void kernel_launch(void* const* d_in, const int* in_sizes, int n_in,
                              void* d_out, int out_size)
{
    const float* x    = (const float*)d_in[0];
    const float* W1   = (const float*)d_in[1];
    const float* b1   = (const float*)d_in[2];
    const float* W2   = (const float*)d_in[3];
    const float* b2   = (const float*)d_in[4];
    const float* leaf = (const float*)d_in[5];
    float* out = (float*)d_out;

    cudaFuncSetAttribute(sdt_fp16_kernel, cudaFuncAttributeMaxDynamicSharedMemorySize, SMEM_BYTES);

    convert_w1_kernel<<<(NTOT * KDIM + 255) / 256, 256>>>(W1);
    sdt_fp16_kernel<<<NCTAS, THREADS, SMEM_BYTES>>>(x, b1, W2, b2, leaf, out);
}

// round 9
// speedup vs baseline: 1.0626x; 1.0626x over previous
#include <cuda_runtime.h>
#include <cuda_fp16.h>
#include <cstdint>

// Soft decision tree forward via mma.sync fp16 (family-common sm_103;
// tcgen05 unavailable in this toolchain path).
// Chain nodes (2^k)-1, k=0..5 -> N = 6*64 = 384.
// GEMM H = X[65536x128] @ W1cat[128x384], fp16 -> fp32 accumulate.
// Fused epilogue: relu -> dot W2 -> sigmoid -> 6-level leaf fold.
// R9: persistent kernel. 128 CTAs x 4 M-tiles. W staged to smem ONCE per CTA;
// X for the next tile cp.async'd (raw fp32) behind the current tile's MMA.

#define THREADS 384      // 12 warps: wm = wid&1 (M half), wn = wid>>1 (node)
#define M_CTA   128
#define KDIM    128
#define NTOT    384
#define NCTAS   128
#define TILES   4
#define XPITCH  288      // bytes/row (72 words): conflict-free lds64 (16-lane phases)
#define WPITCH  288

// W1 (live nodes) fp16, [n=384][k=128], k permuted within 16-blocks so that
// pairs (2t4,2t4+1) and (2t4+8,2t4+9) are adjacent -> B frags = one LDS.64.
__device__ __align__(16) __half g_Wh[NTOT * KDIM];

// ---- smem layout (bytes) ----
#define OFF_B1    0
#define OFF_W2    1536
#define OFF_B2    3072
#define OFF_LEAF  3104
#define OFF_RS    3360                 // rowsum 6*132*4 = 3168 -> 6528
#define OFF_XC    6656                 // converted X: 128 * 288 = 36864
#define OFF_W     43520                // W: 384 * 288 = 110592
#define OFF_XR    154112               // raw X: 128 rows * 512B = 65536
#define SMEM_BYTES 219648              // 214.5 KB, 1 CTA/SM

// ---------------- helpers ----------------
__device__ __forceinline__ uint32_t smem_u32_of(const void* p) {
    uint32_t a;
    asm("{ .reg .u64 t; cvta.to.shared.u64 t, %1; cvt.u32.u64 %0, t; }"
        : "=r"(a) : "l"(p));
    return a;
}
__device__ __forceinline__ void cp_async16(uint32_t dst, const void* src) {
    asm volatile("cp.async.cg.shared.global [%0], [%1], 16;" :: "r"(dst), "l"(src));
}
__device__ __forceinline__ void lds64(uint32_t& a, uint32_t& b, uint32_t addr) {
    asm volatile("ld.shared.v2.u32 {%0,%1}, [%2];" : "=r"(a), "=r"(b) : "r"(addr));
}
__device__ __forceinline__ void sts32(uint32_t addr, uint32_t v) {
    asm volatile("st.shared.u32 [%0], %1;" :: "r"(addr), "r"(v));
}
__device__ __forceinline__ void mma_fp16(float* c, const uint32_t* a,
                                         uint32_t b0, uint32_t b1) {
    asm volatile(
        "mma.sync.aligned.m16n8k16.row.col.f32.f16.f16.f32 "
        "{%0,%1,%2,%3}, {%4,%5,%6,%7}, {%8,%9}, {%0,%1,%2,%3};"
        : "+f"(c[0]), "+f"(c[1]), "+f"(c[2]), "+f"(c[3])
        : "r"(a[0]), "r"(a[1]), "r"(a[2]), "r"(a[3]), "r"(b0), "r"(b1));
}

// ---------------- pre-kernel: W1 -> fp16, permuted k ----------------
__global__ void convert_w1_kernel(const float* __restrict__ W1) {
    int idx = blockIdx.x * blockDim.x + threadIdx.x;
    if (idx >= NTOT * KDIM) return;
    int k = idx & 127;
    int n = idx >> 7;
    int node = n >> 6, h = n & 63;
    int gnode = (1 << node) - 1;            // 0,1,3,7,15,31
    float v = W1[(size_t)gnode * (KDIM * 64) + (size_t)k * 64 + h];
    int blk = k >> 4, kk = k & 15, q = kk >> 1;
    int pos = (q & 3) * 2 + (q >> 2);
    g_Wh[n * KDIM + blk * 16 + pos * 2 + (kk & 1)] = __float2half_rn(v);
}

// ---------------- main kernel ----------------
__global__ __launch_bounds__(THREADS, 1)
void sdt_fp16_kernel(const float* __restrict__ x,
                     const float* __restrict__ b1,
                     const float* __restrict__ W2,
                     const float* __restrict__ b2,
                     const float* __restrict__ leaf,
                     float* __restrict__ out)
{
    extern __shared__ char smem[];
    const uint32_t sbase = smem_u32_of(smem);
    float* b1s    = (float*)(smem + OFF_B1);
    float* W2s    = (float*)(smem + OFF_W2);
    float* b2s    = (float*)(smem + OFF_B2);
    float* leafs  = (float*)(smem + OFF_LEAF);
    float* rowsum = (float*)(smem + OFF_RS);

    const int tid  = threadIdx.x;
    const int lane = tid & 31;
    const int wid  = tid >> 5;
    const int wm   = wid & 1;
    const int wn   = wid >> 1;
    const int g    = lane >> 2;
    const int t4   = lane & 3;

    // ---- prologue: stage W (once) + raw X tile 0 via cp.async ----
    #pragma unroll
    for (int it = 0; it < 16; it++) {
        int idx = tid + it * THREADS;       // 0..6143
        int row = idx >> 4, v = idx & 15;
        cp_async16(sbase + OFF_W + row * WPITCH + v * 16,
                   g_Wh + row * KDIM + v * 8);
    }
    {
        int tile0 = blockIdx.x * TILES;
        const float* xt = x + (size_t)tile0 * M_CTA * KDIM;
        #pragma unroll
        for (int it = 0; it < 11; it++) {
            int idx = tid + it * THREADS;   // 0..4095
            if (idx < 4096) {
                int row = idx >> 5, v = idx & 31;
                cp_async16(sbase + OFF_XR + row * 512 + v * 16,
                           xt + row * KDIM + v * 4);
            }
        }
    }
    asm volatile("cp.async.commit_group;" ::: "memory");

    // small tensors for the 6 live nodes
    for (int i = tid; i < NTOT; i += THREADS) {
        int node = i >> 6, h = i & 63;
        int gl = ((1 << node) - 1) * 64 + h;
        b1s[i] = b1[gl];
        W2s[i] = W2[gl];
    }
    if (tid < 6)  b2s[tid]   = b2[(1 << tid) - 1];
    if (tid < 64) leafs[tid] = leaf[tid];

    asm volatile("cp.async.wait_group 0;" ::: "memory");
    __syncthreads();

    const uint32_t xb   = sbase + OFF_XC + (uint32_t)((wm * 64 + g) * XPITCH + t4 * 8);
    const uint32_t wb   = sbase + OFF_W  + (uint32_t)((wn * 64 + g) * WPITCH + t4 * 8);

    for (int ti = 0; ti < TILES; ti++) {
        const int rowbase = (blockIdx.x * TILES + ti) * M_CTA;

        // ---- convert raw X -> fp16 interleaved Xcvt ----
        #pragma unroll
        for (int it = 0; it < 11; it++) {
            int idx = tid + it * THREADS;   // 0..4095
            if (idx < 4096) {
                int row = idx >> 5, c4 = idx & 31;
                float4 v = *(const float4*)(smem + OFF_XR + row * 512 + c4 * 16);
                __half2 h01 = __floats2half2_rn(v.x, v.y);
                __half2 h23 = __floats2half2_rn(v.z, v.w);
                int blk = c4 >> 2, m = c4 & 3;
                int pos_a = (m & 1) * 4 + (m >> 1);
                uint32_t a = sbase + OFF_XC + row * XPITCH + blk * 32 + pos_a * 4;
                sts32(a,     *(uint32_t*)&h01);
                sts32(a + 8, *(uint32_t*)&h23);
            }
        }
        __syncthreads();

        // ---- prefetch raw X for next tile (overlaps MMA below) ----
        if (ti + 1 < TILES) {
            const float* xt = x + (size_t)(blockIdx.x * TILES + ti + 1) * M_CTA * KDIM;
            #pragma unroll
            for (int it = 0; it < 11; it++) {
                int idx = tid + it * THREADS;
                if (idx < 4096) {
                    int row = idx >> 5, v = idx & 31;
                    cp_async16(sbase + OFF_XR + row * 512 + v * 16,
                               xt + row * KDIM + v * 4);
                }
            }
            asm volatile("cp.async.commit_group;" ::: "memory");
        }

        // ---- MMA: 8 k-steps over full k=128 ----
        float acc[4][8][4];
        #pragma unroll
        for (int mt = 0; mt < 4; mt++)
            #pragma unroll
            for (int nt = 0; nt < 8; nt++)
                #pragma unroll
                for (int j = 0; j < 4; j++) acc[mt][nt][j] = 0.0f;

        #pragma unroll
        for (int ks = 0; ks < 8; ks++) {
            const uint32_t ko = (uint32_t)(ks * 32);
            uint32_t A[4][4];
            #pragma unroll
            for (int mt = 0; mt < 4; mt++) {
                lds64(A[mt][0], A[mt][2], xb + (uint32_t)(mt * 16 * XPITCH) + ko);
                lds64(A[mt][1], A[mt][3], xb + (uint32_t)(mt * 16 * XPITCH) + 8 * XPITCH + ko);
            }
            #pragma unroll
            for (int nt = 0; nt < 8; nt++) {
                uint32_t b0, b1v_;
                lds64(b0, b1v_, wb + (uint32_t)(nt * 8 * WPITCH) + ko);
                #pragma unroll
                for (int mt = 0; mt < 4; mt++)
                    mma_fp16(acc[mt][nt], A[mt], b0, b1v_);
            }
        }

        // ---- fused epilogue ----
        float b1v[16], W2v[16];
        #pragma unroll
        for (int nt = 0; nt < 8; nt++) {
            int col = wn * 64 + nt * 8 + t4 * 2;
            b1v[2 * nt]     = b1s[col];
            b1v[2 * nt + 1] = b1s[col + 1];
            W2v[2 * nt]     = W2s[col];
            W2v[2 * nt + 1] = W2s[col + 1];
        }

        #pragma unroll
        for (int mt = 0; mt < 4; mt++) {
            float s0 = 0.0f, s1 = 0.0f;
            #pragma unroll
            for (int nt = 0; nt < 8; nt++) {
                s0 = fmaf(fmaxf(acc[mt][nt][0] + b1v[2 * nt], 0.0f),     W2v[2 * nt], s0);
                s0 = fmaf(fmaxf(acc[mt][nt][1] + b1v[2 * nt + 1], 0.0f), W2v[2 * nt + 1], s0);
                s1 = fmaf(fmaxf(acc[mt][nt][2] + b1v[2 * nt], 0.0f),     W2v[2 * nt], s1);
                s1 = fmaf(fmaxf(acc[mt][nt][3] + b1v[2 * nt + 1], 0.0f), W2v[2 * nt + 1], s1);
            }
            s0 += __shfl_xor_sync(0xffffffffu, s0, 1);
            s0 += __shfl_xor_sync(0xffffffffu, s0, 2);
            s1 += __shfl_xor_sync(0xffffffffu, s1, 1);
            s1 += __shfl_xor_sync(0xffffffffu, s1, 2);
            if (t4 == 0) {
                int r = wm * 64 + mt * 16 + g;
                rowsum[wn * 132 + r]     = s0;
                rowsum[wn * 132 + r + 8] = s1;
            }
        }
        __syncthreads();

        if (tid < M_CTA) {
            float p[6];
            #pragma unroll
            for (int k = 0; k < 6; k++) {
                float z = rowsum[k * 132 + tid] + b2s[k];
                p[k] = 1.0f / (1.0f + __expf(-z));
            }
            float v[32];
            #pragma unroll
            for (int m = 0; m < 32; m++)
                v[m] = fmaf(p[0], leafs[2 * m + 1], (1.0f - p[0]) * leafs[2 * m]);
            #pragma unroll
            for (int k = 1; k < 6; k++) {
                int len = 32 >> k;
                #pragma unroll
                for (int m = 0; m < 32; m++)
                    if (m < len)
                        v[m] = fmaf(p[k], v[2 * m + 1], (1.0f - p[k]) * v[2 * m]);
            }
            out[rowbase + tid] = v[0];
        }

        // wait for next tile's raw X; sync also closes rowsum/Xcvt reuse hazards
        if (ti + 1 < TILES)
            asm volatile("cp.async.wait_group 0;" ::: "memory");
        __syncthreads();
    }
}

// ---------------- launch ----------------
extern "C" void kernel_launch(void* const* d_in, const int* in_sizes, int n_in,
                              void* d_out, int out_size)
{
    const float* x    = (const float*)d_in[0];
    const float* W1   = (const float*)d_in[1];
    const float* b1   = (const float*)d_in[2];
    const float* W2   = (const float*)d_in[3];
    const float* b2   = (const float*)d_in[4];
    const float* leaf = (const float*)d_in[5];
    float* out = (float*)d_out;

    cudaFuncSetAttribute(sdt_fp16_kernel, cudaFuncAttributeMaxDynamicSharedMemorySize, SMEM_BYTES);

    convert_w1_kernel<<<(NTOT * KDIM + 255) / 256, 256>>>(W1);
    sdt_fp16_kernel<<<NCTAS, THREADS, SMEM_BYTES>>>(x, b1, W2, b2, leaf, out);
}